// round 1
// baseline (speedup 1.0000x reference)
#include <cuda_runtime.h>
#include <math.h>

#define THREADS 256
#define TPB 64          // points per block
#define H 256
#define EMBD 63
#define SX_PITCH 68     // padded pitch for x tile (16B aligned, conflict-mitigating)

// dynamic smem layout (floats):
//  s_emb : 64 rows(e) x 64(pt)        = 4096
//  s_x   : 256 rows(k) x SX_PITCH(pt) = 17408
//  s_w   : 64 rows(k) x 256(j)        = 16384
#define SMEM_FLOATS (64*64 + 256*SX_PITCH + 64*H)

__global__ __launch_bounds__(THREADS, 1)
void mlp3d_kernel(const float* __restrict__ coords,
                  const float* __restrict__ W0, const float* __restrict__ b0,
                  const float* __restrict__ W1, const float* __restrict__ b1,
                  const float* __restrict__ W2, const float* __restrict__ b2,
                  const float* __restrict__ Wocc, const float* __restrict__ bocc,
                  const float* __restrict__ Wc, const float* __restrict__ bc,
                  float* __restrict__ out, int npts)
{
    extern __shared__ float smem[];
    float* s_emb = smem;                       // 64 x 64 (k-major: [e][pt])
    float* s_x   = smem + 64*64;               // 256 x SX_PITCH (k-major: [k][pt])
    float* s_w   = s_x + 256*SX_PITCH;         // 64 x 256 ([k][j])

    const int t = threadIdx.x;
    const int gbase = blockIdx.x * TPB;

    // ---------------- embedding: [x, (sin,cos)x10 per dim] -> s_emb ----------
    if (t < 192) {
        int pt = t & 63, d = t >> 6;           // d in 0..2
        int g = gbase + pt;
        float v = (g < npts) ? coords[g*3 + d] : 0.f;
        s_emb[d*64 + pt] = v;
        float f = 1.f;
        #pragma unroll
        for (int fr = 0; fr < 10; fr++) {
            float s, c;
            sincosf(v * f, &s, &c);
            s_emb[(3 + fr*6 + d)*64 + pt] = s;     // sin block
            s_emb[(6 + fr*6 + d)*64 + pt] = c;     // cos block
            f *= 2.f;
        }
    }
    if (t < 64) s_emb[63*64 + t] = 0.f;        // zero pad row (e = 63)

    // stage W0 (63x256) into s_w, zero row 63
    {
        const float4* src = (const float4*)W0;
        float4* dst = (float4*)s_w;
        #pragma unroll 4
        for (int i = t; i < (EMBD*H)/4; i += THREADS) dst[i] = src[i];
        float4 z = make_float4(0.f,0.f,0.f,0.f);
        for (int i = t; i < H/4; i += THREADS) ((float4*)(s_w + 63*H))[i] = z;
    }
    __syncthreads();

    const int tn = t & 15;     // neuron group: j = tn + 16*i
    const int tp = t >> 4;     // point group: pts 4*tp .. 4*tp+3

    // ---------------- layer 0: x = emb @ W0 + b0 (no activation) -------------
    float acc[4][16];
    #pragma unroll
    for (int q = 0; q < 4; q++)
        #pragma unroll
        for (int i = 0; i < 16; i++) acc[q][i] = 0.f;

    #pragma unroll 4
    for (int k = 0; k < 64; k++) {
        float4 xv = *(const float4*)&s_emb[k*64 + 4*tp];
        float wv[16];
        #pragma unroll
        for (int i = 0; i < 16; i++) wv[i] = s_w[k*H + tn + 16*i];
        #pragma unroll
        for (int i = 0; i < 16; i++) {
            acc[0][i] = fmaf(xv.x, wv[i], acc[0][i]);
            acc[1][i] = fmaf(xv.y, wv[i], acc[1][i]);
            acc[2][i] = fmaf(xv.z, wv[i], acc[2][i]);
            acc[3][i] = fmaf(xv.w, wv[i], acc[3][i]);
        }
    }
    __syncthreads();   // all reads of s_emb / s_w done

    // store x (k-major) into s_x
    #pragma unroll
    for (int i = 0; i < 16; i++) {
        float bb = b0[tn + 16*i];
        #pragma unroll
        for (int q = 0; q < 4; q++)
            s_x[(tn + 16*i)*SX_PITCH + 4*tp + q] = acc[q][i] + bb;
    }
    __syncthreads();

    // ---------------- layer 1 (full h1 for occ trunk) + part branches --------
    // part p only needs k-chunk-p partial sums at j in part p => snapshot deltas.
    float pcls[4][4];  // [pt_local][part]
    #pragma unroll
    for (int q = 0; q < 4; q++)
        #pragma unroll
        for (int c = 0; c < 4; c++) pcls[q][c] = 0.f;

    #pragma unroll
    for (int q = 0; q < 4; q++)
        #pragma unroll
        for (int i = 0; i < 16; i++) acc[q][i] = 0.f;

    #pragma unroll
    for (int c = 0; c < 4; c++) {           // k-chunk (== part index)
        // stage W1 chunk c (rows 64c..64c+63)
        {
            const float4* src = (const float4*)(W1 + c*64*H);
            float4* dst = (float4*)s_w;
            #pragma unroll 4
            for (int i = t; i < (64*H)/4; i += THREADS) dst[i] = src[i];
        }
        __syncthreads();

        float pprev[4][4];                   // snapshot of acc at j in part c
        #pragma unroll
        for (int q = 0; q < 4; q++)
            #pragma unroll
            for (int u = 0; u < 4; u++) pprev[q][u] = acc[q][4*c + u];

        #pragma unroll 2
        for (int k = 0; k < 64; k++) {
            float4 xv = *(const float4*)&s_x[(c*64 + k)*SX_PITCH + 4*tp];
            float wv[16];
            #pragma unroll
            for (int i = 0; i < 16; i++) wv[i] = s_w[k*H + tn + 16*i];
            #pragma unroll
            for (int i = 0; i < 16; i++) {
                acc[0][i] = fmaf(xv.x, wv[i], acc[0][i]);
                acc[1][i] = fmaf(xv.y, wv[i], acc[1][i]);
                acc[2][i] = fmaf(xv.z, wv[i], acc[2][i]);
                acc[3][i] = fmaf(xv.w, wv[i], acc[3][i]);
            }
        }

        // part-c contribution: relu(chunk-delta + b1) . Wc[c]
        #pragma unroll
        for (int u = 0; u < 4; u++) {
            int j = tn + 16*(4*c + u);
            float bb = b1[j];
            float wc = Wc[c*H + j];
            #pragma unroll
            for (int q = 0; q < 4; q++) {
                float pd = acc[q][4*c + u] - pprev[q][u] + bb;
                pcls[q][c] = fmaf(fmaxf(pd, 0.f), wc, pcls[q][c]);
            }
        }
        __syncthreads();   // chunk's s_w reads done before next staging
    }

    // y = relu(h1) overwrites s_x (all s_x reads finished at last barrier)
    #pragma unroll
    for (int i = 0; i < 16; i++) {
        float bb = b1[tn + 16*i];
        #pragma unroll
        for (int q = 0; q < 4; q++)
            s_x[(tn + 16*i)*SX_PITCH + 4*tp + q] = fmaxf(acc[q][i] + bb, 0.f);
    }
    __syncthreads();

    // ---------------- layer 2: z = relu(y @ W2 + b2) -------------------------
    float acc2[4][16];
    #pragma unroll
    for (int q = 0; q < 4; q++)
        #pragma unroll
        for (int i = 0; i < 16; i++) acc2[q][i] = 0.f;

    for (int c = 0; c < 4; c++) {
        {
            const float4* src = (const float4*)(W2 + c*64*H);
            float4* dst = (float4*)s_w;
            #pragma unroll 4
            for (int i = t; i < (64*H)/4; i += THREADS) dst[i] = src[i];
        }
        __syncthreads();

        #pragma unroll 4
        for (int k = 0; k < 64; k++) {
            float4 xv = *(const float4*)&s_x[(c*64 + k)*SX_PITCH + 4*tp];
            float wv[16];
            #pragma unroll
            for (int i = 0; i < 16; i++) wv[i] = s_w[k*H + tn + 16*i];
            #pragma unroll
            for (int i = 0; i < 16; i++) {
                acc2[0][i] = fmaf(xv.x, wv[i], acc2[0][i]);
                acc2[1][i] = fmaf(xv.y, wv[i], acc2[1][i]);
                acc2[2][i] = fmaf(xv.z, wv[i], acc2[2][i]);
                acc2[3][i] = fmaf(xv.w, wv[i], acc2[3][i]);
            }
        }
        __syncthreads();
    }

    // ---------------- occ head ----------------------------------------------
    float oc[4] = {0.f, 0.f, 0.f, 0.f};
    #pragma unroll
    for (int i = 0; i < 16; i++) {
        int j = tn + 16*i;
        float bb = b2[j];
        float wo = Wocc[j];
        #pragma unroll
        for (int q = 0; q < 4; q++)
            oc[q] = fmaf(fmaxf(acc2[q][i] + bb, 0.f), wo, oc[q]);
    }

    // ---------------- reduce across the 16 neuron-group lanes ----------------
    #pragma unroll
    for (int q = 0; q < 4; q++) {
        float v = oc[q];
        #pragma unroll
        for (int off = 8; off; off >>= 1)
            v += __shfl_xor_sync(0xffffffffu, v, off);
        oc[q] = v;
        #pragma unroll
        for (int c = 0; c < 4; c++) {
            float p = pcls[q][c];
            #pragma unroll
            for (int off = 8; off; off >>= 1)
                p += __shfl_xor_sync(0xffffffffu, p, off);
            pcls[q][c] = p;
        }
    }

    if (tn == 0) {
        float bo = bocc[0];
        #pragma unroll
        for (int q = 0; q < 4; q++) {
            int g = gbase + 4*tp + q;
            if (g < npts) {
                out[g] = oc[q] + bo;                       // occ  [N]
                #pragma unroll
                for (int c = 0; c < 4; c++)
                    out[npts + g*4 + c] = pcls[q][c] + bc[c];  // part_class [N,4]
            }
        }
    }
}

extern "C" void kernel_launch(void* const* d_in, const int* in_sizes, int n_in,
                              void* d_out, int out_size)
{
    const float* coords = (const float*)d_in[0];
    const float* W0   = (const float*)d_in[1];
    const float* b0   = (const float*)d_in[2];
    const float* W1   = (const float*)d_in[3];
    const float* b1   = (const float*)d_in[4];
    const float* W2   = (const float*)d_in[5];
    const float* b2   = (const float*)d_in[6];
    const float* Wocc = (const float*)d_in[7];
    const float* bocc = (const float*)d_in[8];
    const float* Wc   = (const float*)d_in[9];
    const float* bc   = (const float*)d_in[10];
    float* out = (float*)d_out;

    int npts = in_sizes[0] / 3;
    int blocks = (npts + TPB - 1) / TPB;
    size_t smem = SMEM_FLOATS * sizeof(float);

    cudaFuncSetAttribute(mlp3d_kernel,
                         cudaFuncAttributeMaxDynamicSharedMemorySize, (int)smem);
    mlp3d_kernel<<<blocks, THREADS, smem>>>(coords, W0, b0, W1, b1, W2, b2,
                                            Wocc, bocc, Wc, bc, out, npts);
    (void)n_in; (void)out_size;
}

// round 2
// speedup vs baseline: 1.2585x; 1.2585x over previous
#include <cuda_runtime.h>
#include <math.h>

#define THREADS 256
#define TPB 64          // points per block
#define H 256
#define SX_PITCH 68     // padded pitch for x tile
#define KC 32           // k-chunk size

// dynamic smem (floats):
//  s_emb : 64 x 64                  = 4096
//  s_x   : 256 x SX_PITCH           = 17408
//  s_w   : 2 buffers of KC x 256    = 16384
#define SMEM_FLOATS (64*64 + 256*SX_PITCH + 2*KC*H)

typedef unsigned long long ull;

__device__ __forceinline__ ull pk2(float a, float b) {
    ull r; asm("mov.b64 %0,{%1,%2};" : "=l"(r) : "f"(a), "f"(b)); return r;
}
__device__ __forceinline__ void upk2(ull v, float& a, float& b) {
    asm("mov.b64 {%0,%1},%2;" : "=f"(a), "=f"(b) : "l"(v));
}
__device__ __forceinline__ void fma2(ull& d, ull a, ull b) {
    asm("fma.rn.f32x2 %0,%1,%2,%3;" : "=l"(d) : "l"(a), "l"(b), "l"(d));
}

__global__ __launch_bounds__(THREADS, 1)
void mlp3d_kernel(const float* __restrict__ coords,
                  const float* __restrict__ W0, const float* __restrict__ b0,
                  const float* __restrict__ W1, const float* __restrict__ b1,
                  const float* __restrict__ W2, const float* __restrict__ b2,
                  const float* __restrict__ Wocc, const float* __restrict__ bocc,
                  const float* __restrict__ Wc, const float* __restrict__ bc,
                  float* __restrict__ out, int npts)
{
    extern __shared__ float smem[];
    float* s_emb = smem;                        // [64 e][64 pt]
    float* s_x   = smem + 64*64;                // [256 k][SX_PITCH pt]
    float* s_w0  = s_x + 256*SX_PITCH;          // buffer 0: [KC][256]
    float* s_w1  = s_w0 + KC*H;                 // buffer 1

    const int t = threadIdx.x;
    const int gbase = blockIdx.x * TPB;
    const int tn = t & 15;      // neuron group: thread owns j = 2*tn + 32*ip + {0,1}, ip=0..7
    const int tp = t >> 4;      // point group: pts 4*tp .. 4*tp+3

    // ---------------- embedding -> s_emb ------------------------------------
    if (t < 192) {
        int pt = t & 63, d = t >> 6;
        int g = gbase + pt;
        float v = (g < npts) ? coords[g*3 + d] : 0.f;
        s_emb[d*64 + pt] = v;
        float f = 1.f;
        #pragma unroll
        for (int fr = 0; fr < 10; fr++) {
            float s, c;
            sincosf(v * f, &s, &c);
            s_emb[(3 + fr*6 + d)*64 + pt] = s;
            s_emb[(6 + fr*6 + d)*64 + pt] = c;
            f *= 2.f;
        }
    }
    if (t < 64) s_emb[63*64 + t] = 0.f;         // pad row e=63

    // ---- stage W0 chunk0 (rows 0-31) -> buf0, chunk1 (rows 32-63, row63=0) -> buf1
    {
        const float4 z = make_float4(0.f,0.f,0.f,0.f);
        const float4* src0 = (const float4*)W0;
        const float4* src1 = (const float4*)(W0 + 32*H);
        float4* d0 = (float4*)s_w0;
        float4* d1 = (float4*)s_w1;
        #pragma unroll
        for (int r = 0; r < 8; r++) {
            int i = t + 256*r;
            d0[i] = src0[i];
            d1[i] = (i < 31*64) ? src1[i] : z;   // 31 valid rows in chunk1
        }
    }
    __syncthreads();

    // ---------------- layer 0: x = emb @ W0 (+b0 at store) -------------------
    ull acc[4][8];
    #pragma unroll
    for (int q = 0; q < 4; q++)
        #pragma unroll
        for (int ip = 0; ip < 8; ip++) acc[q][ip] = 0ull;

    #pragma unroll
    for (int c = 0; c < 2; c++) {
        const float* wb = c ? s_w1 : s_w0;
        #pragma unroll 4
        for (int k = 0; k < KC; k++) {
            float4 xv = *(const float4*)&s_emb[(c*KC + k)*64 + 4*tp];
            ull x0 = pk2(xv.x, xv.x), x1 = pk2(xv.y, xv.y);
            ull x2 = pk2(xv.z, xv.z), x3 = pk2(xv.w, xv.w);
            #pragma unroll
            for (int ip = 0; ip < 8; ip++) {
                ull w = *(const ull*)&wb[k*H + 2*tn + 32*ip];
                fma2(acc[0][ip], x0, w);
                fma2(acc[1][ip], x1, w);
                fma2(acc[2][ip], x2, w);
                fma2(acc[3][ip], x3, w);
            }
        }
    }
    __syncthreads();   // emb/W0 reads done

    // store x (k-major) into s_x, add b0
    #pragma unroll
    for (int ip = 0; ip < 8; ip++) {
        int j0 = 2*tn + 32*ip;
        float bb0 = b0[j0], bb1 = b0[j0+1];
        #pragma unroll
        for (int q = 0; q < 4; q++) {
            float a, b; upk2(acc[q][ip], a, b);
            s_x[j0*SX_PITCH + 4*tp + q]     = a + bb0;
            s_x[(j0+1)*SX_PITCH + 4*tp + q] = b + bb1;
        }
    }
    // stage W1 chunk 0 -> buf0 (exposed once per layer boundary)
    __syncthreads();
    {
        const float4* src = (const float4*)W1;
        float4* d0 = (float4*)s_w0;
        #pragma unroll
        for (int r = 0; r < 8; r++) d0[t + 256*r] = src[t + 256*r];
    }
    __syncthreads();

    // ---------------- layer 1 (+ part branches via chunk-delta snapshots) ----
    float pcls[4][4];
    #pragma unroll
    for (int q = 0; q < 4; q++)
        #pragma unroll
        for (int p = 0; p < 4; p++) pcls[q][p] = 0.f;

    #pragma unroll
    for (int q = 0; q < 4; q++)
        #pragma unroll
        for (int ip = 0; ip < 8; ip++) acc[q][ip] = 0ull;

    ull snap[4][2];   // snapshot of part-p accumulator pairs (ip = 2p, 2p+1)

    #pragma unroll
    for (int c = 0; c < 8; c++) {
        const int p = c >> 1;
        // prefetch next chunk
        float4 pf[8];
        if (c < 7) {
            const float4* src = (const float4*)(W1 + (c+1)*KC*H);
            #pragma unroll
            for (int r = 0; r < 8; r++) pf[r] = src[t + 256*r];
        }
        if ((c & 1) == 0) {        // entering part p: snapshot its pairs
            #pragma unroll
            for (int q = 0; q < 4; q++) {
                snap[q][0] = acc[q][2*p];
                snap[q][1] = acc[q][2*p+1];
            }
        }
        const float* wb = (c & 1) ? s_w1 : s_w0;
        #pragma unroll 4
        for (int k = 0; k < KC; k++) {
            float4 xv = *(const float4*)&s_x[(c*KC + k)*SX_PITCH + 4*tp];
            ull x0 = pk2(xv.x, xv.x), x1 = pk2(xv.y, xv.y);
            ull x2 = pk2(xv.z, xv.z), x3 = pk2(xv.w, xv.w);
            #pragma unroll
            for (int ip = 0; ip < 8; ip++) {
                ull w = *(const ull*)&wb[k*H + 2*tn + 32*ip];
                fma2(acc[0][ip], x0, w);
                fma2(acc[1][ip], x1, w);
                fma2(acc[2][ip], x2, w);
                fma2(acc[3][ip], x3, w);
            }
        }
        if (c & 1) {               // leaving part p: emit class contribution
            #pragma unroll
            for (int ii = 0; ii < 2; ii++) {
                int ip = 2*p + ii;
                int j0 = 2*tn + 32*ip;
                float bb0 = b1[j0], bb1 = b1[j0+1];
                float wc0 = Wc[p*H + j0], wc1 = Wc[p*H + j0 + 1];
                #pragma unroll
                for (int q = 0; q < 4; q++) {
                    float a, b, sa, sb;
                    upk2(acc[q][ip], a, b);
                    upk2(snap[q][ii], sa, sb);
                    float d0 = fmaxf(a - sa + bb0, 0.f);
                    float d1 = fmaxf(b - sb + bb1, 0.f);
                    pcls[q][p] = fmaf(d0, wc0, pcls[q][p]);
                    pcls[q][p] = fmaf(d1, wc1, pcls[q][p]);
                }
            }
        }
        if (c < 7) {
            float4* dst = (float4*)((c & 1) ? s_w0 : s_w1);
            #pragma unroll
            for (int r = 0; r < 8; r++) dst[t + 256*r] = pf[r];
        }
        __syncthreads();
    }

    // y = relu(h1 + b1) overwrites s_x
    #pragma unroll
    for (int ip = 0; ip < 8; ip++) {
        int j0 = 2*tn + 32*ip;
        float bb0 = b1[j0], bb1 = b1[j0+1];
        #pragma unroll
        for (int q = 0; q < 4; q++) {
            float a, b; upk2(acc[q][ip], a, b);
            s_x[j0*SX_PITCH + 4*tp + q]     = fmaxf(a + bb0, 0.f);
            s_x[(j0+1)*SX_PITCH + 4*tp + q] = fmaxf(b + bb1, 0.f);
        }
    }
    __syncthreads();
    // stage W2 chunk 0 -> buf0
    {
        const float4* src = (const float4*)W2;
        float4* d0 = (float4*)s_w0;
        #pragma unroll
        for (int r = 0; r < 8; r++) d0[t + 256*r] = src[t + 256*r];
    }
    __syncthreads();

    // ---------------- layer 2 -------------------------------------------------
    #pragma unroll
    for (int q = 0; q < 4; q++)
        #pragma unroll
        for (int ip = 0; ip < 8; ip++) acc[q][ip] = 0ull;

    #pragma unroll
    for (int c = 0; c < 8; c++) {
        float4 pf[8];
        if (c < 7) {
            const float4* src = (const float4*)(W2 + (c+1)*KC*H);
            #pragma unroll
            for (int r = 0; r < 8; r++) pf[r] = src[t + 256*r];
        }
        const float* wb = (c & 1) ? s_w1 : s_w0;
        #pragma unroll 4
        for (int k = 0; k < KC; k++) {
            float4 xv = *(const float4*)&s_x[(c*KC + k)*SX_PITCH + 4*tp];
            ull x0 = pk2(xv.x, xv.x), x1 = pk2(xv.y, xv.y);
            ull x2 = pk2(xv.z, xv.z), x3 = pk2(xv.w, xv.w);
            #pragma unroll
            for (int ip = 0; ip < 8; ip++) {
                ull w = *(const ull*)&wb[k*H + 2*tn + 32*ip];
                fma2(acc[0][ip], x0, w);
                fma2(acc[1][ip], x1, w);
                fma2(acc[2][ip], x2, w);
                fma2(acc[3][ip], x3, w);
            }
        }
        if (c < 7) {
            float4* dst = (float4*)((c & 1) ? s_w0 : s_w1);
            #pragma unroll
            for (int r = 0; r < 8; r++) dst[t + 256*r] = pf[r];
        }
        __syncthreads();
    }

    // ---------------- occ head ------------------------------------------------
    float oc[4] = {0.f, 0.f, 0.f, 0.f};
    #pragma unroll
    for (int ip = 0; ip < 8; ip++) {
        int j0 = 2*tn + 32*ip;
        float bb0 = b2[j0], bb1 = b2[j0+1];
        float wo0 = Wocc[j0], wo1 = Wocc[j0+1];
        #pragma unroll
        for (int q = 0; q < 4; q++) {
            float a, b; upk2(acc[q][ip], a, b);
            oc[q] = fmaf(fmaxf(a + bb0, 0.f), wo0, oc[q]);
            oc[q] = fmaf(fmaxf(b + bb1, 0.f), wo1, oc[q]);
        }
    }

    // reduce across the 16 neuron-group lanes (tn)
    #pragma unroll
    for (int q = 0; q < 4; q++) {
        float v = oc[q];
        #pragma unroll
        for (int off = 8; off; off >>= 1)
            v += __shfl_xor_sync(0xffffffffu, v, off);
        oc[q] = v;
        #pragma unroll
        for (int p = 0; p < 4; p++) {
            float x = pcls[q][p];
            #pragma unroll
            for (int off = 8; off; off >>= 1)
                x += __shfl_xor_sync(0xffffffffu, x, off);
            pcls[q][p] = x;
        }
    }

    if (tn == 0) {
        float bo = bocc[0];
        #pragma unroll
        for (int q = 0; q < 4; q++) {
            int g = gbase + 4*tp + q;
            if (g < npts) {
                out[g] = oc[q] + bo;                            // occ [N]
                #pragma unroll
                for (int p = 0; p < 4; p++)
                    out[npts + g*4 + p] = pcls[q][p] + bc[p];   // part_class [N,4]
            }
        }
    }
}

extern "C" void kernel_launch(void* const* d_in, const int* in_sizes, int n_in,
                              void* d_out, int out_size)
{
    const float* coords = (const float*)d_in[0];
    const float* W0   = (const float*)d_in[1];
    const float* b0   = (const float*)d_in[2];
    const float* W1   = (const float*)d_in[3];
    const float* b1   = (const float*)d_in[4];
    const float* W2   = (const float*)d_in[5];
    const float* b2   = (const float*)d_in[6];
    const float* Wocc = (const float*)d_in[7];
    const float* bocc = (const float*)d_in[8];
    const float* Wc   = (const float*)d_in[9];
    const float* bc   = (const float*)d_in[10];
    float* out = (float*)d_out;

    int npts = in_sizes[0] / 3;
    int blocks = (npts + TPB - 1) / TPB;
    size_t smem = SMEM_FLOATS * sizeof(float);

    cudaFuncSetAttribute(mlp3d_kernel,
                         cudaFuncAttributeMaxDynamicSharedMemorySize, (int)smem);
    mlp3d_kernel<<<blocks, THREADS, smem>>>(coords, W0, b0, W1, b1, W2, b2,
                                            Wocc, bocc, Wc, bc, out, npts);
    (void)n_in; (void)out_size;
}

// round 4
// speedup vs baseline: 2.0419x; 1.6225x over previous
#include <cuda_runtime.h>
#include <cuda_bf16.h>
#include <math.h>
#include <stdint.h>

// ---------------------------------------------------------------------------
// Geometry
#define THREADS   512
#define MPB       128          // points per block
// k-permutation within a 16-group: pairs (2t,2t+1,2t+8,2t+9) become contiguous
__host__ __device__ __forceinline__ int perm16(int k) {
    return ((k >> 1) & 3) * 4 + (k & 1) + ((k >> 3) & 1) * 2;
}
__host__ __device__ __forceinline__ int permpos(int k) {   // k in 0..255
    return (k & ~15) + perm16(k & 15);
}

// smem byte offsets
#define PX        528u                 // x row pitch bytes (264 halves)
#define PW        144u                 // w row pitch bytes (72 halves)
#define X_PLANE   67584u               // 128 * 528
#define OFF_X1    0u
#define OFF_X2    67584u
#define OFF_W     135168u              // hi plane 36864B then lo plane 36864B
#define W_PLANE   36864u
#define OFF_BIAS  208896u              // 2053 floats
#define OFF_PART  217120u              // 128*4*2 floats
#define OFF_OCC   221216u              // 128*2 floats
#define SMEM_TOTAL 222496u

// bias smem float indices
#define SB_B0   0
#define SB_B1   256
#define SB_B2   512
#define SB_WOCC 768
#define SB_WC   1024
#define SB_BC   2048
#define SB_BOCC 2052

// ---------------------------------------------------------------------------
// prepped weights: [plane hi/lo][n rows][72 halves] images, flat-copy ready
__device__ __align__(16) __nv_bfloat16 g_B0[2][256 * 72];        // W0^T  (k chunk0, row63 zero)
__device__ __align__(16) __nv_bfloat16 g_B1[4][2][256 * 72];     // W1^T 4 k-chunks
__device__ __align__(16) __nv_bfloat16 g_B2[4][2][256 * 72];     // W2^T 4 k-chunks
__device__ __align__(16) __nv_bfloat16 g_BP[4][2][64 * 72];      // W1 diag part blocks

// ---------------------------------------------------------------------------
__device__ __forceinline__ uint32_t smem_u32(const void* p) {
    uint32_t a;
    asm("{ .reg .u64 t; cvta.to.shared.u64 t, %1; cvt.u32.u64 %0, t; }" : "=r"(a) : "l"(p));
    return a;
}
__device__ __forceinline__ void lds64(uint32_t addr, uint32_t& x, uint32_t& y) {
    asm volatile("ld.shared.v2.b32 {%0,%1}, [%2];" : "=r"(x), "=r"(y) : "r"(addr));
}
__device__ __forceinline__ void mma16816(float* c, uint32_t a0, uint32_t a1,
                                         uint32_t a2, uint32_t a3,
                                         uint32_t b0, uint32_t b1) {
    asm volatile(
        "mma.sync.aligned.m16n8k16.row.col.f32.bf16.bf16.f32 "
        "{%0,%1,%2,%3}, {%4,%5,%6,%7}, {%8,%9}, {%0,%1,%2,%3};"
        : "+f"(c[0]), "+f"(c[1]), "+f"(c[2]), "+f"(c[3])
        : "r"(a0), "r"(a1), "r"(a2), "r"(a3), "r"(b0), "r"(b1));
}
__device__ __forceinline__ void bsplit(float v, uint16_t& h, uint16_t& l) {
    __nv_bfloat16 bh = __float2bfloat16(v);
    __nv_bfloat16 bl = __float2bfloat16(v - __bfloat162float(bh));
    h = __bfloat16_as_ushort(bh);
    l = __bfloat16_as_ushort(bl);
}

// ---------------------------------------------------------------------------
// prep: transpose + bf16-split + k-permute weights into smem-image buffers
__global__ void prep_kernel(const float* __restrict__ W0,
                            const float* __restrict__ W1,
                            const float* __restrict__ W2)
{
    int i = blockIdx.x * THREADS + threadIdx.x;       // 163840 total
    float v; __nv_bfloat16 *dh, *dl; int dst;
    if (i < 16384) {                                   // W0^T
        int n = i >> 6, kl = i & 63;
        v = (kl < 63) ? W0[kl * 256 + n] : 0.f;
        dst = n * 72 + permpos(kl);
        dh = g_B0[0]; dl = g_B0[1];
    } else if (i < 16384 + 65536) {                    // W1^T chunks
        int t2 = i - 16384;
        int c = t2 >> 14, n = (t2 >> 6) & 255, kl = t2 & 63;
        v = W1[(c * 64 + kl) * 256 + n];
        dst = n * 72 + permpos(kl);
        dh = g_B1[c][0]; dl = g_B1[c][1];
    } else if (i < 16384 + 2 * 65536) {                // W2^T chunks
        int t2 = i - 16384 - 65536;
        int c = t2 >> 14, n = (t2 >> 6) & 255, kl = t2 & 63;
        v = W2[(c * 64 + kl) * 256 + n];
        dst = n * 72 + permpos(kl);
        dh = g_B2[c][0]; dl = g_B2[c][1];
    } else {                                           // W1 diag part blocks
        int t2 = i - 16384 - 2 * 65536;
        int p = t2 >> 12, jl = (t2 >> 6) & 63, kl = t2 & 63;
        v = W1[(64 * p + kl) * 256 + (64 * p + jl)];
        dst = jl * 72 + permpos(kl);
        dh = g_BP[p][0]; dl = g_BP[p][1];
    }
    uint16_t h, l; bsplit(v, h, l);
    dh[dst] = __ushort_as_bfloat16(h);
    dl[dst] = __ushort_as_bfloat16(l);
}

// ---------------------------------------------------------------------------
// one k-chunk (4 k-tiles) of 3-term MMA into NT n-tile accumulators
template<int NT>
__device__ __forceinline__ void mma_chunk(float acc[][4],
                                          uint32_t ax0, uint32_t ax1,  // A hi rows g / g+8 (chunk base incl.)
                                          uint32_t wbase,              // B hi base for this warp
                                          uint32_t w_plane_off)        // hi->lo plane distance
{
    #pragma unroll
    for (int kt = 0; kt < 4; kt++) {
        uint32_t ao = kt * 32;
        uint32_t ah0, ah2, ah1, ah3, al0, al2, al1, al3;
        lds64(ax0 + ao,            ah0, ah2);
        lds64(ax1 + ao,            ah1, ah3);
        lds64(ax0 + ao + X_PLANE,  al0, al2);
        lds64(ax1 + ao + X_PLANE,  al1, al3);
        uint32_t wb = wbase + kt * 32;
        #pragma unroll
        for (int nt = 0; nt < NT; nt++) {
            uint32_t bh0, bh1, bl0, bl1;
            lds64(wb,               bh0, bh1);
            lds64(wb + w_plane_off, bl0, bl1);
            mma16816(acc[nt], ah0, ah1, ah2, ah3, bh0, bh1);
            mma16816(acc[nt], al0, al1, al2, al3, bh0, bh1);
            mma16816(acc[nt], ah0, ah1, ah2, ah3, bl0, bl1);
            wb += 8 * PW;
        }
    }
}

// ---------------------------------------------------------------------------
__global__ __launch_bounds__(THREADS, 1)
void mlp3d_mma(const float* __restrict__ coords,
               const float* __restrict__ b0, const float* __restrict__ b1,
               const float* __restrict__ b2,
               const float* __restrict__ Wocc, const float* __restrict__ bocc,
               const float* __restrict__ Wc, const float* __restrict__ bc,
               float* __restrict__ out, int npts)
{
    extern __shared__ char sm[];
    char*  sx1 = sm + OFF_X1;
    char*  sx2 = sm + OFF_X2;
    float* s_bias = (float*)(sm + OFF_BIAS);
    float* s_part = (float*)(sm + OFF_PART);   // [m][p][h]
    float* s_occ  = (float*)(sm + OFF_OCC);    // [m][h]
    const uint32_t smb = smem_u32(sm);

    const int t = threadIdx.x;
    const int warp = t >> 5, lane = t & 31;
    const int s = warp & 7;            // m-strip (rows 16s..16s+15)
    const int h = warp >> 3;           // n-half (cols 128h..)
    const int g = lane >> 2, tg = lane & 3;
    const int gbase = blockIdx.x * MPB;

    // fragment base addresses
    const uint32_t ax0 = smb + OFF_X1 + (uint32_t)(16 * s + g) * PX + 8 * tg;
    const uint32_t ax1 = ax0 + 8 * PX;
    const uint32_t wmain = smb + OFF_W + (uint32_t)(h * 128 + g) * PW + 8 * tg;

    // ---- preload biases/heads into smem ----
    for (int i = t; i < 2053; i += THREADS) {
        float v;
        if      (i < 256)  v = b0[i];
        else if (i < 512)  v = b1[i - 256];
        else if (i < 768)  v = b2[i - 512];
        else if (i < 1024) v = Wocc[i - 768];
        else if (i < 2048) v = Wc[i - 1024];
        else if (i < 2052) v = bc[i - 2048];
        else               v = bocc[0];
        s_bias[i] = v;
    }

    // ---- embedding -> x chunk0 (k-permuted, hi/lo planes) ----
    if (t < 384) {
        int pt = t & 127, d = t >> 7;
        int eg = gbase + pt;
        float v = (eg < npts) ? coords[eg * 3 + d] : 0.f;
        char* r1 = sx1 + pt * PX;
        char* r2 = sx2 + pt * PX;
        uint16_t hh, ll;
        bsplit(v, hh, ll);
        int p0 = permpos(d);
        *(uint16_t*)(r1 + 2 * p0) = hh; *(uint16_t*)(r2 + 2 * p0) = ll;
        float f = 1.f;
        #pragma unroll
        for (int fr = 0; fr < 10; fr++) {
            float sv, cv;
            sincosf(v * f, &sv, &cv);
            int ps = permpos(3 + fr * 6 + d);
            int pc = permpos(6 + fr * 6 + d);
            bsplit(sv, hh, ll);
            *(uint16_t*)(r1 + 2 * ps) = hh; *(uint16_t*)(r2 + 2 * ps) = ll;
            bsplit(cv, hh, ll);
            *(uint16_t*)(r1 + 2 * pc) = hh; *(uint16_t*)(r2 + 2 * pc) = ll;
            f *= 2.f;
        }
    }
    if (t < 128) {   // zero pad k=63 (perm pos 63)
        *(uint16_t*)(sx1 + t * PX + 2 * 63) = 0;
        *(uint16_t*)(sx2 + t * PX + 2 * 63) = 0;
    }

    // ---- stage W0 image ----
    {
        const float4* src = (const float4*)g_B0;
        float4* dst = (float4*)(sm + OFF_W);
        #pragma unroll
        for (int r = 0; r < 9; r++) dst[t + THREADS * r] = src[t + THREADS * r];
    }
    __syncthreads();

    float acc[16][4];

    // ================= layer 0 : x = emb @ W0 + b0 (no relu) ================
    #pragma unroll
    for (int nt = 0; nt < 16; nt++)
        #pragma unroll
        for (int u = 0; u < 4; u++) acc[nt][u] = 0.f;
    mma_chunk<16>(acc, ax0, ax1, wmain, W_PLANE);
    __syncthreads();   // everyone done reading emb before overwrite

    #pragma unroll
    for (int nt = 0; nt < 16; nt++) {
        int j0 = h * 128 + nt * 8 + 2 * tg;
        float bb0 = s_bias[SB_B0 + j0], bb1 = s_bias[SB_B0 + j0 + 1];
        int kp = (j0 & ~15) * 2 + (perm16(j0 & 15)) * 2;   // byte offset of pair
        uint16_t h0, l0, h1, l1;
        float v00 = acc[nt][0] + bb0, v01 = acc[nt][1] + bb1;
        float v10 = acc[nt][2] + bb0, v11 = acc[nt][3] + bb1;
        int r0 = 16 * s + g, r1 = r0 + 8;
        bsplit(v00, h0, l0); bsplit(v01, h1, l1);
        *(uint32_t*)(sx1 + r0 * PX + kp) = (uint32_t)h0 | ((uint32_t)h1 << 16);
        *(uint32_t*)(sx2 + r0 * PX + kp) = (uint32_t)l0 | ((uint32_t)l1 << 16);
        bsplit(v10, h0, l0); bsplit(v11, h1, l1);
        *(uint32_t*)(sx1 + r1 * PX + kp) = (uint32_t)h0 | ((uint32_t)h1 << 16);
        *(uint32_t*)(sx2 + r1 * PX + kp) = (uint32_t)l0 | ((uint32_t)l1 << 16);
    }
    __syncthreads();

    // ================= layer 1 main : h1 = x @ W1 + b1 =======================
    #pragma unroll
    for (int nt = 0; nt < 16; nt++)
        #pragma unroll
        for (int u = 0; u < 4; u++) acc[nt][u] = 0.f;

    for (int c = 0; c < 4; c++) {
        const float4* src = (const float4*)g_B1[c];
        float4* dst = (float4*)(sm + OFF_W);
        #pragma unroll
        for (int r = 0; r < 9; r++) dst[t + THREADS * r] = src[t + THREADS * r];
        __syncthreads();
        mma_chunk<16>(acc, ax0 + c * 128, ax1 + c * 128, wmain, W_PLANE);
        __syncthreads();
    }

    // ---- part branches: 4 exact 64x64 sub-GEMMs + class heads ----
    {
        const float4* src = (const float4*)g_BP;
        float4* dst = (float4*)(sm + OFF_W);
        #pragma unroll
        for (int r = 0; r < 9; r++) dst[t + THREADS * r] = src[t + THREADS * r];
        __syncthreads();
    }
    #pragma unroll
    for (int p = 0; p < 4; p++) {
        float pacc[4][4];
        #pragma unroll
        for (int nt = 0; nt < 4; nt++)
            #pragma unroll
            for (int u = 0; u < 4; u++) pacc[nt][u] = 0.f;
        uint32_t wp = smb + OFF_W + (uint32_t)p * 18432u
                    + (uint32_t)(32 * h + g) * PW + 8 * tg;
        mma_chunk<4>(pacc, ax0 + p * 128, ax1 + p * 128, wp, 9216u);
        // class head p: relu(pacc + b1) . Wc[p]
        float r0s = 0.f, r1s = 0.f;
        #pragma unroll
        for (int nt = 0; nt < 4; nt++) {
            int j0 = 64 * p + 32 * h + nt * 8 + 2 * tg;
            float bb0 = s_bias[SB_B1 + j0], bb1 = s_bias[SB_B1 + j0 + 1];
            float wc0 = s_bias[SB_WC + p * 256 + j0], wc1 = s_bias[SB_WC + p * 256 + j0 + 1];
            r0s = fmaf(fmaxf(pacc[nt][0] + bb0, 0.f), wc0, r0s);
            r0s = fmaf(fmaxf(pacc[nt][1] + bb1, 0.f), wc1, r0s);
            r1s = fmaf(fmaxf(pacc[nt][2] + bb0, 0.f), wc0, r1s);
            r1s = fmaf(fmaxf(pacc[nt][3] + bb1, 0.f), wc1, r1s);
        }
        r0s += __shfl_xor_sync(0xffffffffu, r0s, 1);
        r0s += __shfl_xor_sync(0xffffffffu, r0s, 2);
        r1s += __shfl_xor_sync(0xffffffffu, r1s, 1);
        r1s += __shfl_xor_sync(0xffffffffu, r1s, 2);
        if (tg == 0) {
            s_part[(16 * s + g) * 8 + p * 2 + h]     = r0s;
            s_part[(16 * s + 8 + g) * 8 + p * 2 + h] = r1s;
        }
    }
    __syncthreads();   // parts done reading s_x before epilogue overwrite

    // epilogue L1: y = relu(h1 + b1) -> s_x
    #pragma unroll
    for (int nt = 0; nt < 16; nt++) {
        int j0 = h * 128 + nt * 8 + 2 * tg;
        float bb0 = s_bias[SB_B1 + j0], bb1 = s_bias[SB_B1 + j0 + 1];
        int kp = (j0 & ~15) * 2 + (perm16(j0 & 15)) * 2;
        uint16_t h0, l0, h1, l1;
        float v00 = fmaxf(acc[nt][0] + bb0, 0.f), v01 = fmaxf(acc[nt][1] + bb1, 0.f);
        float v10 = fmaxf(acc[nt][2] + bb0, 0.f), v11 = fmaxf(acc[nt][3] + bb1, 0.f);
        int r0 = 16 * s + g, r1 = r0 + 8;
        bsplit(v00, h0, l0); bsplit(v01, h1, l1);
        *(uint32_t*)(sx1 + r0 * PX + kp) = (uint32_t)h0 | ((uint32_t)h1 << 16);
        *(uint32_t*)(sx2 + r0 * PX + kp) = (uint32_t)l0 | ((uint32_t)l1 << 16);
        bsplit(v10, h0, l0); bsplit(v11, h1, l1);
        *(uint32_t*)(sx1 + r1 * PX + kp) = (uint32_t)h0 | ((uint32_t)h1 << 16);
        *(uint32_t*)(sx2 + r1 * PX + kp) = (uint32_t)l0 | ((uint32_t)l1 << 16);
    }
    __syncthreads();

    // ================= layer 2 : z = relu(y @ W2 + b2) =======================
    #pragma unroll
    for (int nt = 0; nt < 16; nt++)
        #pragma unroll
        for (int u = 0; u < 4; u++) acc[nt][u] = 0.f;

    for (int c = 0; c < 4; c++) {
        const float4* src = (const float4*)g_B2[c];
        float4* dst = (float4*)(sm + OFF_W);
        #pragma unroll
        for (int r = 0; r < 9; r++) dst[t + THREADS * r] = src[t + THREADS * r];
        __syncthreads();
        mma_chunk<16>(acc, ax0 + c * 128, ax1 + c * 128, wmain, W_PLANE);
        __syncthreads();
    }

    // ---- occ head ----
    {
        float r0s = 0.f, r1s = 0.f;
        #pragma unroll
        for (int nt = 0; nt < 16; nt++) {
            int j0 = h * 128 + nt * 8 + 2 * tg;
            float bb0 = s_bias[SB_B2 + j0], bb1 = s_bias[SB_B2 + j0 + 1];
            float wo0 = s_bias[SB_WOCC + j0], wo1 = s_bias[SB_WOCC + j0 + 1];
            r0s = fmaf(fmaxf(acc[nt][0] + bb0, 0.f), wo0, r0s);
            r0s = fmaf(fmaxf(acc[nt][1] + bb1, 0.f), wo1, r0s);
            r1s = fmaf(fmaxf(acc[nt][2] + bb0, 0.f), wo0, r1s);
            r1s = fmaf(fmaxf(acc[nt][3] + bb1, 0.f), wo1, r1s);
        }
        r0s += __shfl_xor_sync(0xffffffffu, r0s, 1);
        r0s += __shfl_xor_sync(0xffffffffu, r0s, 2);
        r1s += __shfl_xor_sync(0xffffffffu, r1s, 1);
        r1s += __shfl_xor_sync(0xffffffffu, r1s, 2);
        if (tg == 0) {
            s_occ[(16 * s + g) * 2 + h]     = r0s;
            s_occ[(16 * s + 8 + g) * 2 + h] = r1s;
        }
    }
    __syncthreads();

    // ---- final stores ----
    if (t < 128) {
        int gm = gbase + t;
        if (gm < npts)
            out[gm] = s_occ[2 * t] + s_occ[2 * t + 1] + s_bias[SB_BOCC];
    }
    {
        int m = t >> 2, p = t & 3;
        int gm = gbase + m;
        if (gm < npts)
            out[npts + gm * 4 + p] =
                s_part[m * 8 + p * 2] + s_part[m * 8 + p * 2 + 1] + s_bias[SB_BC + p];
    }
}

// ---------------------------------------------------------------------------
extern "C" void kernel_launch(void* const* d_in, const int* in_sizes, int n_in,
                              void* d_out, int out_size)
{
    const float* coords = (const float*)d_in[0];
    const float* W0   = (const float*)d_in[1];
    const float* b0   = (const float*)d_in[2];
    const float* W1   = (const float*)d_in[3];
    const float* b1   = (const float*)d_in[4];
    const float* W2   = (const float*)d_in[5];
    const float* b2   = (const float*)d_in[6];
    const float* Wocc = (const float*)d_in[7];
    const float* bocc = (const float*)d_in[8];
    const float* Wc   = (const float*)d_in[9];
    const float* bc   = (const float*)d_in[10];
    float* out = (float*)d_out;

    int npts = in_sizes[0] / 3;
    int blocks = (npts + MPB - 1) / MPB;

    prep_kernel<<<320, THREADS>>>(W0, W1, W2);

    cudaFuncSetAttribute(mlp3d_mma, cudaFuncAttributeMaxDynamicSharedMemorySize,
                         (int)SMEM_TOTAL);
    mlp3d_mma<<<blocks, THREADS, SMEM_TOTAL>>>(coords, b0, b1, b2, Wocc, bocc,
                                               Wc, bc, out, npts);
    (void)n_in; (void)out_size;
}

// round 5
// speedup vs baseline: 3.1371x; 1.5364x over previous
#include <cuda_runtime.h>
#include <cuda_fp16.h>
#include <math.h>
#include <stdint.h>

// ---------------------------------------------------------------------------
#define THREADS   512
#define MPB       128            // points per block
// k-permutation within each 16-group: pairs (2t,2t+1,2t+8,2t+9) contiguous
__host__ __device__ __forceinline__ int perm16(int k) {
    return ((k >> 1) & 3) * 4 + (k & 1) + ((k >> 3) & 1) * 2;
}
__host__ __device__ __forceinline__ int permpos(int k) {
    return (k & ~15) + perm16(k & 15);
}

// smem byte offsets
#define PX        528u           // X row pitch (256 halves + pad)
#define PW        144u           // W row pitch (72 halves)
#define X_PLANE   67584u         // 128 * PX
#define OFF_X1    0u             // A hi plane
#define OFF_X2    67584u         // A lo plane
#define OFF_W     135168u        // W buffer: 256 rows x 144B = 36864
#define W_BYTES   36864u
#define OFF_BIAS  172032u        // 2053 floats (pad to 8224)
#define OFF_PART  180256u        // 128*4*4 floats = 8192
#define OFF_OCC   188448u        // 128*4 floats  = 2048
#define SMEM_TOTAL 190496u

#define SB_B0   0
#define SB_B1   256
#define SB_B2   512
#define SB_WOCC 768
#define SB_WC   1024
#define SB_BC   2048
#define SB_BOCC 2052

// ---------------------------------------------------------------------------
// prepped fp16 weight images (single hi plane), smem-image layout, flat-copy
__device__ __align__(16) __half g_W0[256 * 72];        // W0^T (k-chunk0, row63=0)
__device__ __align__(16) __half g_W1[4][256 * 72];     // W1^T 4 k-chunks
__device__ __align__(16) __half g_W2[4][256 * 72];     // W2^T 4 k-chunks
__device__ __align__(16) __half g_WP[4 * 64 * 72];     // W1 diag part blocks

// ---------------------------------------------------------------------------
__device__ __forceinline__ uint32_t smem_u32(const void* p) {
    uint32_t a;
    asm("{ .reg .u64 t; cvta.to.shared.u64 t, %1; cvt.u32.u64 %0, t; }" : "=r"(a) : "l"(p));
    return a;
}
__device__ __forceinline__ void lds64(uint32_t addr, uint32_t& x, uint32_t& y) {
    asm volatile("ld.shared.v2.b32 {%0,%1}, [%2];" : "=r"(x), "=r"(y) : "r"(addr));
}
__device__ __forceinline__ void mma16816(float* c, uint32_t a0, uint32_t a1,
                                         uint32_t a2, uint32_t a3,
                                         uint32_t b0, uint32_t b1) {
    asm volatile(
        "mma.sync.aligned.m16n8k16.row.col.f32.f16.f16.f32 "
        "{%0,%1,%2,%3}, {%4,%5,%6,%7}, {%8,%9}, {%0,%1,%2,%3};"
        : "+f"(c[0]), "+f"(c[1]), "+f"(c[2]), "+f"(c[3])
        : "r"(a0), "r"(a1), "r"(a2), "r"(a3), "r"(b0), "r"(b1));
}
__device__ __forceinline__ void hsplit(float v, uint16_t& h, uint16_t& l) {
    __half hh = __float2half_rn(v);
    __half ll = __float2half_rn(v - __half2float(hh));
    h = __half_as_ushort(hh);
    l = __half_as_ushort(ll);
}

// ---------------------------------------------------------------------------
__global__ void prep_kernel(const float* __restrict__ W0,
                            const float* __restrict__ W1,
                            const float* __restrict__ W2)
{
    int i = blockIdx.x * THREADS + threadIdx.x;     // 163840 total
    float v; __half* d; int dst;
    if (i < 16384) {                                 // W0^T
        int n = i >> 6, kl = i & 63;
        v = (kl < 63) ? W0[kl * 256 + n] : 0.f;
        dst = n * 72 + permpos(kl);
        d = g_W0;
    } else if (i < 16384 + 65536) {                  // W1^T
        int t2 = i - 16384;
        int c = t2 >> 14, n = (t2 >> 6) & 255, kl = t2 & 63;
        v = W1[(c * 64 + kl) * 256 + n];
        dst = n * 72 + permpos(kl);
        d = g_W1[c];
    } else if (i < 16384 + 2 * 65536) {              // W2^T
        int t2 = i - 16384 - 65536;
        int c = t2 >> 14, n = (t2 >> 6) & 255, kl = t2 & 63;
        v = W2[(c * 64 + kl) * 256 + n];
        dst = n * 72 + permpos(kl);
        d = g_W2[c];
    } else {                                         // W1 diag part blocks
        int t2 = i - 16384 - 2 * 65536;
        int p = t2 >> 12, jl = (t2 >> 6) & 63, kl = t2 & 63;
        v = W1[(64 * p + kl) * 256 + (64 * p + jl)];
        dst = (p * 64 + jl) * 72 + permpos(kl);
        d = g_WP;
    }
    d[dst] = __float2half_rn(v);
}

// ---------------------------------------------------------------------------
// register-prefetch staging of a 36864B weight image
__device__ __forceinline__ void pf_ldg(float4 pf[5], const __half* src, int t) {
    const float4* s = (const float4*)src;
    #pragma unroll
    for (int r = 0; r < 4; r++) pf[r] = s[t + 512 * r];
    if (t < 256) pf[4] = s[t + 2048];
}
__device__ __forceinline__ void pf_sts(const float4 pf[5], char* wbuf, int t) {
    float4* d = (float4*)wbuf;
    #pragma unroll
    for (int r = 0; r < 4; r++) d[t + 512 * r] = pf[r];
    if (t < 256) d[t + 2048] = pf[4];
}

// ---------------------------------------------------------------------------
// one 64-k chunk, 2-term fp16 MMA. acc[2 mt][NNT nt][4]
template<int NNT>
__device__ __forceinline__ void mma2(float acc[2][NNT][4],
                                     uint32_t abase,   // row (32ms+g), +8tg, +chunk off
                                     uint32_t wbase)   // w row (..+g), +8tg
{
    #pragma unroll
    for (int kt = 0; kt < 4; kt++) {
        uint32_t ah[2][4], al[2][4];
        #pragma unroll
        for (int mt = 0; mt < 2; mt++) {
            uint32_t base = abase + mt * (16 * PX) + kt * 32;
            lds64(base,                 ah[mt][0], ah[mt][2]);
            lds64(base + 8 * PX,        ah[mt][1], ah[mt][3]);
            lds64(base + X_PLANE,           al[mt][0], al[mt][2]);
            lds64(base + 8 * PX + X_PLANE,  al[mt][1], al[mt][3]);
        }
        #pragma unroll
        for (int nt = 0; nt < NNT; nt++) {
            uint32_t b0, b1;
            lds64(wbase + nt * (8 * PW) + kt * 32, b0, b1);
            #pragma unroll
            for (int mt = 0; mt < 2; mt++) {
                mma16816(acc[mt][nt], ah[mt][0], ah[mt][1], ah[mt][2], ah[mt][3], b0, b1);
                mma16816(acc[mt][nt], al[mt][0], al[mt][1], al[mt][2], al[mt][3], b0, b1);
            }
        }
    }
}

// ---------------------------------------------------------------------------
__global__ __launch_bounds__(THREADS, 1)
void mlp3d_mma(const float* __restrict__ coords,
               const float* __restrict__ b0, const float* __restrict__ b1,
               const float* __restrict__ b2,
               const float* __restrict__ Wocc, const float* __restrict__ bocc,
               const float* __restrict__ Wc, const float* __restrict__ bc,
               float* __restrict__ out, int npts)
{
    extern __shared__ char sm[];
    char*  sx1 = sm + OFF_X1;
    char*  sx2 = sm + OFF_X2;
    char*  swb = sm + OFF_W;
    float* s_bias = (float*)(sm + OFF_BIAS);
    float* s_part = (float*)(sm + OFF_PART);   // [m][p][ns]
    float* s_occ  = (float*)(sm + OFF_OCC);    // [m][ns]
    const uint32_t smb = smem_u32(sm);

    const int t = threadIdx.x;
    const int warp = t >> 5, lane = t & 31;
    const int ms = warp & 3;            // m-strip: rows 32ms..32ms+31
    const int ns = warp >> 2;           // n-strip: cols 64ns..64ns+63
    const int g = lane >> 2, tg = lane & 3;
    const int gbase = blockIdx.x * MPB;

    const uint32_t abase = smb + OFF_X1 + (uint32_t)(32 * ms + g) * PX + 8 * tg;
    const uint32_t wmain = smb + OFF_W + (uint32_t)(64 * ns + g) * PW + 8 * tg;

    float4 pf[5];
    pf_ldg(pf, g_W0, t);

    // ---- biases/heads -> smem ----
    for (int i = t; i < 2053; i += THREADS) {
        float v;
        if      (i < 256)  v = b0[i];
        else if (i < 512)  v = b1[i - 256];
        else if (i < 768)  v = b2[i - 512];
        else if (i < 1024) v = Wocc[i - 768];
        else if (i < 2048) v = Wc[i - 1024];
        else if (i < 2052) v = bc[i - 2048];
        else               v = bocc[0];
        s_bias[i] = v;
    }

    // ---- embedding -> X chunk0 (k-permuted, hi/lo fp16 planes) ----
    if (t < 384) {
        int pt = t & 127, d = t >> 7;
        int eg = gbase + pt;
        float v = (eg < npts) ? coords[eg * 3 + d] : 0.f;
        char* r1 = sx1 + pt * PX;
        char* r2 = sx2 + pt * PX;
        uint16_t hh, ll;
        hsplit(v, hh, ll);
        int p0 = permpos(d);
        *(uint16_t*)(r1 + 2 * p0) = hh; *(uint16_t*)(r2 + 2 * p0) = ll;
        float f = 1.f;
        #pragma unroll
        for (int fr = 0; fr < 10; fr++) {
            float sv, cv;
            sincosf(v * f, &sv, &cv);
            int ps = permpos(3 + fr * 6 + d);
            int pc = permpos(6 + fr * 6 + d);
            hsplit(sv, hh, ll);
            *(uint16_t*)(r1 + 2 * ps) = hh; *(uint16_t*)(r2 + 2 * ps) = ll;
            hsplit(cv, hh, ll);
            *(uint16_t*)(r1 + 2 * pc) = hh; *(uint16_t*)(r2 + 2 * pc) = ll;
            f *= 2.f;
        }
    }
    if (t < 128) {   // pad k=63
        *(uint16_t*)(sx1 + t * PX + 2 * 63) = 0;
        *(uint16_t*)(sx2 + t * PX + 2 * 63) = 0;
    }
    pf_sts(pf, swb, t);           // W0 into buffer
    __syncthreads();

    float acc[2][8][4];

    // ================= layer 0 ==============================================
    #pragma unroll
    for (int mt = 0; mt < 2; mt++)
        #pragma unroll
        for (int nt = 0; nt < 8; nt++)
            #pragma unroll
            for (int u = 0; u < 4; u++) acc[mt][nt][u] = 0.f;
    pf_ldg(pf, g_W1[0], t);
    mma2<8>(acc, abase, wmain);
    __syncthreads();              // emb reads + W0 reads done

    // epi L0: x = acc + b0 (no relu) -> X ; stage W1c0
    #pragma unroll
    for (int mt = 0; mt < 2; mt++) {
        int r0 = 32 * ms + 16 * mt + g;
        #pragma unroll
        for (int nt = 0; nt < 8; nt++) {
            int j0 = 64 * ns + 8 * nt + 2 * tg;
            int kp = (j0 & ~15) * 2 + perm16(j0 & 15) * 2;
            float bb0 = s_bias[SB_B0 + j0], bb1 = s_bias[SB_B0 + j0 + 1];
            uint16_t h0, l0, h1, l1;
            hsplit(acc[mt][nt][0] + bb0, h0, l0);
            hsplit(acc[mt][nt][1] + bb1, h1, l1);
            *(uint32_t*)(sx1 + r0 * PX + kp) = (uint32_t)h0 | ((uint32_t)h1 << 16);
            *(uint32_t*)(sx2 + r0 * PX + kp) = (uint32_t)l0 | ((uint32_t)l1 << 16);
            hsplit(acc[mt][nt][2] + bb0, h0, l0);
            hsplit(acc[mt][nt][3] + bb1, h1, l1);
            *(uint32_t*)(sx1 + (r0 + 8) * PX + kp) = (uint32_t)h0 | ((uint32_t)h1 << 16);
            *(uint32_t*)(sx2 + (r0 + 8) * PX + kp) = (uint32_t)l0 | ((uint32_t)l1 << 16);
        }
    }
    pf_sts(pf, swb, t);
    __syncthreads();

    // ================= layer 1 main ========================================
    #pragma unroll
    for (int mt = 0; mt < 2; mt++)
        #pragma unroll
        for (int nt = 0; nt < 8; nt++)
            #pragma unroll
            for (int u = 0; u < 4; u++) acc[mt][nt][u] = 0.f;

    #pragma unroll
    for (int c = 0; c < 4; c++) {
        if (c < 3) pf_ldg(pf, g_W1[c + 1], t);
        else       pf_ldg(pf, g_WP, t);
        mma2<8>(acc, abase + c * 128, wmain);
        __syncthreads();
        pf_sts(pf, swb, t);
        __syncthreads();
    }

    // ---- part branches (buffer = WP) ----
    #pragma unroll
    for (int p = 0; p < 4; p++) {
        float pacc[2][2][4];
        #pragma unroll
        for (int mt = 0; mt < 2; mt++)
            #pragma unroll
            for (int nt = 0; nt < 2; nt++)
                #pragma unroll
                for (int u = 0; u < 4; u++) pacc[mt][nt][u] = 0.f;
        uint32_t wp = smb + OFF_W + (uint32_t)(p * 64 + 16 * ns + g) * PW + 8 * tg;
        mma2<2>(pacc, abase + p * 128, wp);
        // class head p
        float rs[2][2] = {{0.f, 0.f}, {0.f, 0.f}};
        #pragma unroll
        for (int mt = 0; mt < 2; mt++)
            #pragma unroll
            for (int nt = 0; nt < 2; nt++) {
                int j0 = 64 * p + 16 * ns + 8 * nt + 2 * tg;
                float bb0 = s_bias[SB_B1 + j0], bb1 = s_bias[SB_B1 + j0 + 1];
                float wc0 = s_bias[SB_WC + p * 256 + j0];
                float wc1 = s_bias[SB_WC + p * 256 + j0 + 1];
                rs[mt][0] = fmaf(fmaxf(pacc[mt][nt][0] + bb0, 0.f), wc0, rs[mt][0]);
                rs[mt][0] = fmaf(fmaxf(pacc[mt][nt][1] + bb1, 0.f), wc1, rs[mt][0]);
                rs[mt][1] = fmaf(fmaxf(pacc[mt][nt][2] + bb0, 0.f), wc0, rs[mt][1]);
                rs[mt][1] = fmaf(fmaxf(pacc[mt][nt][3] + bb1, 0.f), wc1, rs[mt][1]);
            }
        #pragma unroll
        for (int mt = 0; mt < 2; mt++) {
            rs[mt][0] += __shfl_xor_sync(0xffffffffu, rs[mt][0], 1);
            rs[mt][0] += __shfl_xor_sync(0xffffffffu, rs[mt][0], 2);
            rs[mt][1] += __shfl_xor_sync(0xffffffffu, rs[mt][1], 1);
            rs[mt][1] += __shfl_xor_sync(0xffffffffu, rs[mt][1], 2);
            if (tg == 0) {
                int r0 = 32 * ms + 16 * mt + g;
                s_part[r0 * 16 + p * 4 + ns]       = rs[mt][0];
                s_part[(r0 + 8) * 16 + p * 4 + ns] = rs[mt][1];
            }
        }
    }
    __syncthreads();    // part X reads + WP reads done

    // epi L1: y = relu(acc + b1) -> X ; then stage W2c0
    pf_ldg(pf, g_W2[0], t);
    #pragma unroll
    for (int mt = 0; mt < 2; mt++) {
        int r0 = 32 * ms + 16 * mt + g;
        #pragma unroll
        for (int nt = 0; nt < 8; nt++) {
            int j0 = 64 * ns + 8 * nt + 2 * tg;
            int kp = (j0 & ~15) * 2 + perm16(j0 & 15) * 2;
            float bb0 = s_bias[SB_B1 + j0], bb1 = s_bias[SB_B1 + j0 + 1];
            uint16_t h0, l0, h1, l1;
            hsplit(fmaxf(acc[mt][nt][0] + bb0, 0.f), h0, l0);
            hsplit(fmaxf(acc[mt][nt][1] + bb1, 0.f), h1, l1);
            *(uint32_t*)(sx1 + r0 * PX + kp) = (uint32_t)h0 | ((uint32_t)h1 << 16);
            *(uint32_t*)(sx2 + r0 * PX + kp) = (uint32_t)l0 | ((uint32_t)l1 << 16);
            hsplit(fmaxf(acc[mt][nt][2] + bb0, 0.f), h0, l0);
            hsplit(fmaxf(acc[mt][nt][3] + bb1, 0.f), h1, l1);
            *(uint32_t*)(sx1 + (r0 + 8) * PX + kp) = (uint32_t)h0 | ((uint32_t)h1 << 16);
            *(uint32_t*)(sx2 + (r0 + 8) * PX + kp) = (uint32_t)l0 | ((uint32_t)l1 << 16);
        }
    }
    pf_sts(pf, swb, t);
    __syncthreads();

    // ================= layer 2 =============================================
    #pragma unroll
    for (int mt = 0; mt < 2; mt++)
        #pragma unroll
        for (int nt = 0; nt < 8; nt++)
            #pragma unroll
            for (int u = 0; u < 4; u++) acc[mt][nt][u] = 0.f;

    #pragma unroll
    for (int c = 0; c < 4; c++) {
        if (c < 3) pf_ldg(pf, g_W2[c + 1], t);
        mma2<8>(acc, abase + c * 128, wmain);
        __syncthreads();
        if (c < 3) { pf_sts(pf, swb, t); __syncthreads(); }
    }

    // ---- occ head ----
    {
        float rs[2][2] = {{0.f, 0.f}, {0.f, 0.f}};
        #pragma unroll
        for (int mt = 0; mt < 2; mt++)
            #pragma unroll
            for (int nt = 0; nt < 8; nt++) {
                int j0 = 64 * ns + 8 * nt + 2 * tg;
                float bb0 = s_bias[SB_B2 + j0], bb1 = s_bias[SB_B2 + j0 + 1];
                float wo0 = s_bias[SB_WOCC + j0], wo1 = s_bias[SB_WOCC + j0 + 1];
                rs[mt][0] = fmaf(fmaxf(acc[mt][nt][0] + bb0, 0.f), wo0, rs[mt][0]);
                rs[mt][0] = fmaf(fmaxf(acc[mt][nt][1] + bb1, 0.f), wo1, rs[mt][0]);
                rs[mt][1] = fmaf(fmaxf(acc[mt][nt][2] + bb0, 0.f), wo0, rs[mt][1]);
                rs[mt][1] = fmaf(fmaxf(acc[mt][nt][3] + bb1, 0.f), wo1, rs[mt][1]);
            }
        #pragma unroll
        for (int mt = 0; mt < 2; mt++) {
            rs[mt][0] += __shfl_xor_sync(0xffffffffu, rs[mt][0], 1);
            rs[mt][0] += __shfl_xor_sync(0xffffffffu, rs[mt][0], 2);
            rs[mt][1] += __shfl_xor_sync(0xffffffffu, rs[mt][1], 1);
            rs[mt][1] += __shfl_xor_sync(0xffffffffu, rs[mt][1], 2);
            if (tg == 0) {
                int r0 = 32 * ms + 16 * mt + g;
                s_occ[r0 * 4 + ns]       = rs[mt][0];
                s_occ[(r0 + 8) * 4 + ns] = rs[mt][1];
            }
        }
    }
    __syncthreads();

    // ---- final stores ----
    if (t < 128) {
        int gm = gbase + t;
        if (gm < npts)
            out[gm] = s_occ[4 * t] + s_occ[4 * t + 1] + s_occ[4 * t + 2]
                    + s_occ[4 * t + 3] + s_bias[SB_BOCC];
    }
    {
        int m = t >> 2, p = t & 3;
        int gm = gbase + m;
        if (gm < npts)
            out[npts + gm * 4 + p] =
                s_part[m * 16 + p * 4 + 0] + s_part[m * 16 + p * 4 + 1] +
                s_part[m * 16 + p * 4 + 2] + s_part[m * 16 + p * 4 + 3] +
                s_bias[SB_BC + p];
    }
}

// ---------------------------------------------------------------------------
extern "C" void kernel_launch(void* const* d_in, const int* in_sizes, int n_in,
                              void* d_out, int out_size)
{
    const float* coords = (const float*)d_in[0];
    const float* W0   = (const float*)d_in[1];
    const float* b0   = (const float*)d_in[2];
    const float* W1   = (const float*)d_in[3];
    const float* b1   = (const float*)d_in[4];
    const float* W2   = (const float*)d_in[5];
    const float* b2   = (const float*)d_in[6];
    const float* Wocc = (const float*)d_in[7];
    const float* bocc = (const float*)d_in[8];
    const float* Wc   = (const float*)d_in[9];
    const float* bc   = (const float*)d_in[10];
    float* out = (float*)d_out;

    int npts = in_sizes[0] / 3;
    int blocks = (npts + MPB - 1) / MPB;

    prep_kernel<<<320, THREADS>>>(W0, W1, W2);

    cudaFuncSetAttribute(mlp3d_mma, cudaFuncAttributeMaxDynamicSharedMemorySize,
                         (int)SMEM_TOTAL);
    mlp3d_mma<<<blocks, THREADS, SMEM_TOTAL>>>(coords, b0, b1, b2, Wocc, bocc,
                                               Wc, bc, out, npts);
    (void)n_in; (void)out_size;
}